// round 1
// baseline (speedup 1.0000x reference)
#include <cuda_runtime.h>
#include <math.h>

#define BB 32
#define HH 32
#define DM 4096
#define DK 128
#define SINK 4
#define WINDOW 1020
#define MAXC (SINK + WINDOW)   // 1024

// ---------------- device scratch (no allocs allowed) ----------------
__device__ float g_Q  [BB * DM];
__device__ float g_Kn [BB * DM];
__device__ float g_Vn [BB * DM];
__device__ float g_ctx[BB * DM];
__device__ float g_part[6 * BB * DM];     // max(3 weights * 2 ksplit, 1 weight * 4 ksplit) slabs
__device__ float g_cos[MAXC * 64];
__device__ float g_sin[MAXC * 64];

// ---------------- helpers: packed f32x2 FMA ----------------
__device__ __forceinline__ unsigned long long pk2(float a, float b) {
    unsigned long long r;
    asm("mov.b64 %0, {%1, %2};" : "=l"(r) : "f"(a), "f"(b));
    return r;
}
__device__ __forceinline__ void fma2(unsigned long long &acc, unsigned long long x, unsigned long long w) {
    asm("fma.rn.f32x2 %0, %1, %2, %0;" : "+l"(acc) : "l"(x), "l"(w));
}
__device__ __forceinline__ float2 upk2(unsigned long long v) {
    float2 r;
    asm("mov.b64 {%0, %1}, %2;" : "=f"(r.x), "=f"(r.y) : "l"(v));
    return r;
}

// ---------------- RoPE cos/sin table: pos in [0,1024), j in [0,64) ----------------
__global__ void rope_table_kernel() {
    int idx = blockIdx.x * 256 + threadIdx.x;   // 65536 entries
    int pos = idx >> 6;
    int j   = idx & 63;
    float theta = powf(10000.0f, -(float)j / 64.0f);
    float m = (float)pos * theta;
    float s, c;
    sincosf(m, &s, &c);
    g_cos[idx] = c;
    g_sin[idx] = s;
}

// ---------------- skinny GEMM: out[b][n] = sum_k X[b][k] * W[n][k] ----------------
// grid: (DM/128, nWeights, kSplit). block: 128 threads, thread owns one n, all 32 b.
// Writes partials to g_part[(y*gridDim.z + z) slab]. X==nullptr means read g_ctx.
#define CK 256
#define PITCH 34

__global__ void skinny_gemm_kernel(const float* __restrict__ X,
                                   const float* __restrict__ W0,
                                   const float* __restrict__ W1,
                                   const float* __restrict__ W2,
                                   int klen)
{
    __shared__ float xs[CK * PITCH];
    const float* Xp = X ? X : g_ctx;
    const float* W  = (blockIdx.y == 0) ? W0 : (blockIdx.y == 1) ? W1 : W2;
    const int n     = blockIdx.x * 128 + threadIdx.x;
    const int kbase = blockIdx.z * klen;

    unsigned long long acc[16];
#pragma unroll
    for (int p = 0; p < 16; p++) acc[p] = 0ull;

    for (int kc = 0; kc < klen; kc += CK) {
        // cooperative tile load: xs[k][b], coalesced over k
#pragma unroll
        for (int it = 0; it < (CK * BB) / 128; it++) {
            int i = threadIdx.x + it * 128;
            int k = i & (CK - 1);
            int b = i >> 8;                 // i / CK, CK == 256
            xs[k * PITCH + b] = Xp[b * DM + kbase + kc + k];
        }
        __syncthreads();

        const float4* w4p = (const float4*)(W + (size_t)n * DM + kbase + kc);
#pragma unroll 2
        for (int k4 = 0; k4 < CK / 4; k4++) {
            float4 w4 = w4p[k4];
            unsigned long long wx = pk2(w4.x, w4.x);
            unsigned long long wy = pk2(w4.y, w4.y);
            unsigned long long wz = pk2(w4.z, w4.z);
            unsigned long long ww = pk2(w4.w, w4.w);
            const float* xk = xs + (k4 * 4) * PITCH;
            const unsigned long long* x0 = (const unsigned long long*)(xk);
            const unsigned long long* x1 = (const unsigned long long*)(xk + PITCH);
            const unsigned long long* x2 = (const unsigned long long*)(xk + 2 * PITCH);
            const unsigned long long* x3 = (const unsigned long long*)(xk + 3 * PITCH);
#pragma unroll
            for (int p = 0; p < 16; p++) {
                fma2(acc[p], x0[p], wx);
                fma2(acc[p], x1[p], wy);
                fma2(acc[p], x2[p], wz);
                fma2(acc[p], x3[p], ww);
            }
        }
        __syncthreads();
    }

    const int slab = (blockIdx.y * gridDim.z + blockIdx.z) * (BB * DM);
#pragma unroll
    for (int p = 0; p < 16; p++) {
        float2 v = upk2(acc[p]);
        g_part[slab + (2 * p)     * DM + n] = v.x;
        g_part[slab + (2 * p + 1) * DM + n] = v.y;
    }
}

// reduce 2 k-split partials for the 3 QKV projections into g_Q / g_Kn / g_Vn
__global__ void qkv_reduce_kernel() {
    int i = blockIdx.x * 256 + threadIdx.x;   // 3 * 32 * 4096 = 393216
    int y = i / (BB * DM);
    int r = i - y * (BB * DM);
    float v = g_part[(y * 2 + 0) * (BB * DM) + r] + g_part[(y * 2 + 1) * (BB * DM) + r];
    float* dst = (y == 0) ? g_Q : (y == 1) ? g_Kn : g_Vn;
    dst[r] = v;
}

// reduce 4 k-split partials for the output projection straight into d_out
__global__ void o_reduce_kernel(float* __restrict__ out) {
    int i = blockIdx.x * 256 + threadIdx.x;   // 131072
    float v = g_part[i] + g_part[(BB * DM) + i] + g_part[2 * (BB * DM) + i] + g_part[3 * (BB * DM) + i];
    out[i] = v;
}

// ---------------- attention: one block per (b, h), streams K and V once ----------------
__global__ void attn_kernel(const float* __restrict__ kcache,
                            const float* __restrict__ vcache,
                            const int* __restrict__ seqp)
{
    __shared__ float s_sc[MAXC];
    __shared__ float s_q[DK];
    __shared__ float s_qr[DK];
    __shared__ float s_red[8];
    __shared__ float s_b[2];
    __shared__ float s_acc[2][DK];

    const int h = blockIdx.x, b = blockIdx.y;
    const int tid  = threadIdx.x;
    const int lane = tid & 31;
    const int warp = tid >> 5;

    const int seq = *seqp;
    int L, ii;
    if (seq < MAXC) { L = seq + 1; ii = seq; }
    else            { L = MAXC;    ii = SINK + (seq - SINK) % WINDOW; }
    const int qpos = L - 1;
    const int bh = b * HH + h;

    // ---- load + RoPE Q (position qpos), fold in 1/sqrt(DK) ----
    if (tid < DK) s_q[tid] = g_Q[b * DM + h * DK + tid];
    __syncthreads();
    if (tid < DK) {
        int j = tid & 63;
        float flip = (tid < 64) ? -s_q[tid + 64] : s_q[tid - 64];
        float c = g_cos[qpos * 64 + j];
        float s = g_sin[qpos * 64 + j];
        s_qr[tid] = (s_q[tid] * c + flip * s) * 0.08838834764831843f;  // 1/sqrt(128)
    }
    __syncthreads();

    // ---- scores: one warp per cache slot, RoPE K on the fly ----
    const float4 q4 = ((const float4*)s_qr)[lane];
    const float  sgn = (lane < 16) ? -1.0f : 1.0f;
    const int    j16 = lane & 15;
    const float* kbp  = kcache + (size_t)bh * MAXC * DK;
    const float* knew = g_Kn + b * DM + h * DK;

    for (int c0 = warp; c0 < L; c0 += 8) {
        const float* krow = (c0 == ii) ? knew : (kbp + (size_t)c0 * DK);
        float4 kv = ((const float4*)krow)[lane];
        int pos;
        if (seq < MAXC) pos = c0;
        else pos = (c0 < SINK) ? c0
                 : (c0 > ii)   ? (SINK + c0 - ii - 1)
                               : (c0 + (MAXC - 1 - ii));
        float4 cs = ((const float4*)(g_cos + pos * 64))[j16];
        float4 sn = ((const float4*)(g_sin + pos * 64))[j16];
        float fx = sgn * __shfl_xor_sync(0xffffffffu, kv.x, 16);
        float fy = sgn * __shfl_xor_sync(0xffffffffu, kv.y, 16);
        float fz = sgn * __shfl_xor_sync(0xffffffffu, kv.z, 16);
        float fw = sgn * __shfl_xor_sync(0xffffffffu, kv.w, 16);
        float rx = kv.x * cs.x + fx * sn.x;
        float ry = kv.y * cs.y + fy * sn.y;
        float rz = kv.z * cs.z + fz * sn.z;
        float rw = kv.w * cs.w + fw * sn.w;
        float d = q4.x * rx + q4.y * ry + q4.z * rz + q4.w * rw;
#pragma unroll
        for (int o = 16; o; o >>= 1) d += __shfl_xor_sync(0xffffffffu, d, o);
        if (lane == 0) s_sc[c0] = d;
    }
    __syncthreads();

    // ---- softmax (max, exp, sum) ----
    float lmax = -1e30f;
    for (int c = tid; c < L; c += 256) lmax = fmaxf(lmax, s_sc[c]);
#pragma unroll
    for (int o = 16; o; o >>= 1) lmax = fmaxf(lmax, __shfl_xor_sync(0xffffffffu, lmax, o));
    if (lane == 0) s_red[warp] = lmax;
    __syncthreads();
    if (warp == 0) {
        float m = (lane < 8) ? s_red[lane] : -1e30f;
#pragma unroll
        for (int o = 4; o; o >>= 1) m = fmaxf(m, __shfl_xor_sync(0xffffffffu, m, o));
        if (lane == 0) s_b[0] = m;
    }
    __syncthreads();
    const float gmax = s_b[0];

    float lsum = 0.0f;
    for (int c = tid; c < L; c += 256) {
        float e = __expf(s_sc[c] - gmax);
        s_sc[c] = e;
        lsum += e;
    }
#pragma unroll
    for (int o = 16; o; o >>= 1) lsum += __shfl_xor_sync(0xffffffffu, lsum, o);
    if (lane == 0) s_red[warp] = lsum;
    __syncthreads();
    if (warp == 0) {
        float m = (lane < 8) ? s_red[lane] : 0.0f;
#pragma unroll
        for (int o = 4; o; o >>= 1) m += __shfl_xor_sync(0xffffffffu, m, o);
        if (lane == 0) s_b[1] = m;
    }
    __syncthreads();
    const float inv = 1.0f / s_b[1];

    // ---- AV: 128 dims x 2 c-parity groups, coalesced over d ----
    const int d    = tid & 127;
    const int half = tid >> 7;
    const float* vbp  = vcache + (size_t)bh * MAXC * DK;
    const float* vnew = g_Vn + b * DM + h * DK;
    float a0 = 0.0f, a1 = 0.0f;
    int c = half;
#pragma unroll 4
    for (; c + 2 < L; c += 4) {
        const float* vr0 = (c == ii)     ? vnew : vbp + (size_t)c * DK;
        const float* vr1 = (c + 2 == ii) ? vnew : vbp + (size_t)(c + 2) * DK;
        a0 += s_sc[c] * vr0[d];
        a1 += s_sc[c + 2] * vr1[d];
    }
    for (; c < L; c += 2) {
        const float* vr = (c == ii) ? vnew : vbp + (size_t)c * DK;
        a0 += s_sc[c] * vr[d];
    }
    s_acc[half][d] = a0 + a1;
    __syncthreads();
    if (tid < DK)
        g_ctx[b * DM + h * DK + tid] = (s_acc[0][tid] + s_acc[1][tid]) * inv;
}

// ---------------- launch ----------------
extern "C" void kernel_launch(void* const* d_in, const int* in_sizes, int n_in,
                              void* d_out, int out_size)
{
    const float* x_new   = (const float*)d_in[0];
    const float* k_cache = (const float*)d_in[1];
    const float* v_cache = (const float*)d_in[2];
    const float* W_Q     = (const float*)d_in[3];
    const float* W_K     = (const float*)d_in[4];
    const float* W_V     = (const float*)d_in[5];
    const float* W_O     = (const float*)d_in[6];
    const int*   seq_len = (const int*)  d_in[7];
    float* out = (float*)d_out;

    // 1. RoPE cos/sin table (1024 x 64)
    rope_table_kernel<<<256, 256>>>();

    // 2. QKV projections: 3 weights x 2 k-splits of 2048
    skinny_gemm_kernel<<<dim3(DM / 128, 3, 2), 128>>>(x_new, W_Q, W_K, W_V, 2048);
    qkv_reduce_kernel<<<(3 * BB * DM) / 256, 256>>>();

    // 3. attention over the streaming window (no physical reorder needed)
    attn_kernel<<<dim3(HH, BB), 256>>>(k_cache, v_cache, seq_len);

    // 4. output projection: 1 weight x 4 k-splits of 1024, then reduce into d_out
    skinny_gemm_kernel<<<dim3(DM / 128, 1, 4), 128>>>(nullptr, W_O, W_O, W_O, 1024);
    o_reduce_kernel<<<(BB * DM) / 256, 256>>>(out);
}

// round 2
// speedup vs baseline: 1.3999x; 1.3999x over previous
#include <cuda_runtime.h>
#include <math.h>

#define BB 32
#define HH 32
#define DM 4096
#define DK 128
#define SINK 4
#define WINDOW 1020
#define MAXC (SINK + WINDOW)   // 1024

// ---------------- device scratch (no allocs allowed) ----------------
__device__ float g_Q  [BB * DM];
__device__ float g_Kn [BB * DM];
__device__ float g_Vn [BB * DM];
__device__ float g_ctx[BB * DM];
__device__ float g_part[24 * BB * DM];    // 3 weights * 8 ksplit slabs (QKV); O reuses 8
__device__ float g_cos[MAXC * 64];
__device__ float g_sin[MAXC * 64];

// ---------------- helpers: packed f32x2 FMA ----------------
__device__ __forceinline__ unsigned long long pk2(float a, float b) {
    unsigned long long r;
    asm("mov.b64 %0, {%1, %2};" : "=l"(r) : "f"(a), "f"(b));
    return r;
}
__device__ __forceinline__ void fma2(unsigned long long &acc, unsigned long long x, unsigned long long w) {
    asm("fma.rn.f32x2 %0, %1, %2, %0;" : "+l"(acc) : "l"(x), "l"(w));
}
__device__ __forceinline__ float2 upk2(unsigned long long v) {
    float2 r;
    asm("mov.b64 {%0, %1}, %2;" : "=f"(r.x), "=f"(r.y) : "l"(v));
    return r;
}

// ---------------- RoPE cos/sin table: pos in [0,1024), j in [0,64) ----------------
__global__ void rope_table_kernel() {
    int idx = blockIdx.x * 256 + threadIdx.x;   // 65536 entries
    int pos = idx >> 6;
    int j   = idx & 63;
    float theta = powf(10000.0f, -(float)j / 64.0f);
    float m = (float)pos * theta;
    float s, c;
    sincosf(m, &s, &c);
    g_cos[idx] = c;
    g_sin[idx] = s;
}

// ---------------- skinny GEMM: out[b][n] = sum_k X[b][k] * W[n][k] ----------------
// grid: (DM/128, nWeights, kSplit). block: 128 threads, thread owns one n, all 32 b.
#define CK 128
#define PITCH 34

__global__ void __launch_bounds__(128) skinny_gemm_kernel(
                                   const float* __restrict__ X,
                                   const float* __restrict__ W0,
                                   const float* __restrict__ W1,
                                   const float* __restrict__ W2,
                                   int klen)
{
    __shared__ float xs[CK * PITCH];
    const float* Xp = X ? X : g_ctx;
    const float* W  = (blockIdx.y == 0) ? W0 : (blockIdx.y == 1) ? W1 : W2;
    const int n     = blockIdx.x * 128 + threadIdx.x;
    const int kbase = blockIdx.z * klen;

    unsigned long long acc[16];
#pragma unroll
    for (int p = 0; p < 16; p++) acc[p] = 0ull;

    for (int kc = 0; kc < klen; kc += CK) {
        // cooperative tile load: xs[k][b]; thread tid loads column k=tid for every b
#pragma unroll
        for (int it = 0; it < BB; it++) {
            xs[threadIdx.x * PITCH + it] = Xp[it * DM + kbase + kc + threadIdx.x];
        }
        __syncthreads();

        const float4* w4p = (const float4*)(W + (size_t)n * DM + kbase + kc);
#pragma unroll 4
        for (int k4 = 0; k4 < CK / 4; k4++) {
            float4 w4 = w4p[k4];
            unsigned long long wx = pk2(w4.x, w4.x);
            unsigned long long wy = pk2(w4.y, w4.y);
            unsigned long long wz = pk2(w4.z, w4.z);
            unsigned long long ww = pk2(w4.w, w4.w);
            const float* xk = xs + (k4 * 4) * PITCH;
            const unsigned long long* x0 = (const unsigned long long*)(xk);
            const unsigned long long* x1 = (const unsigned long long*)(xk + PITCH);
            const unsigned long long* x2 = (const unsigned long long*)(xk + 2 * PITCH);
            const unsigned long long* x3 = (const unsigned long long*)(xk + 3 * PITCH);
#pragma unroll
            for (int p = 0; p < 16; p++) {
                fma2(acc[p], x0[p], wx);
                fma2(acc[p], x1[p], wy);
                fma2(acc[p], x2[p], wz);
                fma2(acc[p], x3[p], ww);
            }
        }
        __syncthreads();
    }

    const int slab = (blockIdx.y * gridDim.z + blockIdx.z) * (BB * DM);
#pragma unroll
    for (int p = 0; p < 16; p++) {
        float2 v = upk2(acc[p]);
        g_part[slab + (2 * p)     * DM + n] = v.x;
        g_part[slab + (2 * p + 1) * DM + n] = v.y;
    }
}

// reduce 8 k-split partials for the 3 QKV projections into g_Q / g_Kn / g_Vn
__global__ void qkv_reduce_kernel() {
    int i = blockIdx.x * 256 + threadIdx.x;   // 3 * 32 * 4096 = 393216
    int y = i / (BB * DM);
    int r = i - y * (BB * DM);
    float v = 0.0f;
#pragma unroll
    for (int z = 0; z < 8; z++) v += g_part[(y * 8 + z) * (BB * DM) + r];
    float* dst = (y == 0) ? g_Q : (y == 1) ? g_Kn : g_Vn;
    dst[r] = v;
}

// reduce 8 k-split partials for the output projection straight into d_out
__global__ void o_reduce_kernel(float* __restrict__ out) {
    int i = blockIdx.x * 256 + threadIdx.x;   // 131072
    float v = 0.0f;
#pragma unroll
    for (int z = 0; z < 8; z++) v += g_part[z * (BB * DM) + i];
    out[i] = v;
}

// ---------------- attention: one block per (b, h), streams K and V once ----------------
__global__ void __launch_bounds__(256) attn_kernel(
                            const float* __restrict__ kcache,
                            const float* __restrict__ vcache,
                            const int* __restrict__ seqp)
{
    __shared__ float s_sc[MAXC];
    __shared__ float s_q[DK];
    __shared__ float s_qr[DK];
    __shared__ float s_red[8];
    __shared__ float s_b[2];
    __shared__ float s_acc[2][DK];

    const int h = blockIdx.x, b = blockIdx.y;
    const int tid  = threadIdx.x;
    const int lane = tid & 31;
    const int warp = tid >> 5;

    const int seq = *seqp;
    int L, ii;
    if (seq < MAXC) { L = seq + 1; ii = seq; }
    else            { L = MAXC;    ii = SINK + (seq - SINK) % WINDOW; }
    const int qpos = L - 1;
    const int bh = b * HH + h;

    // ---- load + RoPE Q (position qpos), fold in 1/sqrt(DK) ----
    if (tid < DK) s_q[tid] = g_Q[b * DM + h * DK + tid];
    __syncthreads();
    if (tid < DK) {
        int j = tid & 63;
        float flip = (tid < 64) ? -s_q[tid + 64] : s_q[tid - 64];
        float c = g_cos[qpos * 64 + j];
        float s = g_sin[qpos * 64 + j];
        s_qr[tid] = (s_q[tid] * c + flip * s) * 0.08838834764831843f;  // 1/sqrt(128)
    }
    __syncthreads();

    // ---- scores: one warp per cache slot, 2 slots in flight, RoPE K on the fly ----
    const float4 q4 = ((const float4*)s_qr)[lane];
    const float  sgn = (lane < 16) ? -1.0f : 1.0f;
    const int    j16 = lane & 15;
    const float* kbp  = kcache + (size_t)bh * MAXC * DK;
    const float* knew = g_Kn + b * DM + h * DK;

    int c0 = warp;
    for (; c0 + 8 < L; c0 += 16) {
        const int cA = c0, cB = c0 + 8;
        const float* krA = (cA == ii) ? knew : (kbp + (size_t)cA * DK);
        const float* krB = (cB == ii) ? knew : (kbp + (size_t)cB * DK);
        float4 kA = ((const float4*)krA)[lane];
        float4 kB = ((const float4*)krB)[lane];
        int pA, pB;
        if (seq < MAXC) { pA = cA; pB = cB; }
        else {
            pA = (cA < SINK) ? cA : (cA > ii) ? (SINK + cA - ii - 1) : (cA + (MAXC - 1 - ii));
            pB = (cB < SINK) ? cB : (cB > ii) ? (SINK + cB - ii - 1) : (cB + (MAXC - 1 - ii));
        }
        float4 csA = ((const float4*)(g_cos + pA * 64))[j16];
        float4 snA = ((const float4*)(g_sin + pA * 64))[j16];
        float4 csB = ((const float4*)(g_cos + pB * 64))[j16];
        float4 snB = ((const float4*)(g_sin + pB * 64))[j16];
        float dA, dB;
        {
            float fx = sgn * __shfl_xor_sync(0xffffffffu, kA.x, 16);
            float fy = sgn * __shfl_xor_sync(0xffffffffu, kA.y, 16);
            float fz = sgn * __shfl_xor_sync(0xffffffffu, kA.z, 16);
            float fw = sgn * __shfl_xor_sync(0xffffffffu, kA.w, 16);
            dA = q4.x * (kA.x * csA.x + fx * snA.x) + q4.y * (kA.y * csA.y + fy * snA.y)
               + q4.z * (kA.z * csA.z + fz * snA.z) + q4.w * (kA.w * csA.w + fw * snA.w);
        }
        {
            float fx = sgn * __shfl_xor_sync(0xffffffffu, kB.x, 16);
            float fy = sgn * __shfl_xor_sync(0xffffffffu, kB.y, 16);
            float fz = sgn * __shfl_xor_sync(0xffffffffu, kB.z, 16);
            float fw = sgn * __shfl_xor_sync(0xffffffffu, kB.w, 16);
            dB = q4.x * (kB.x * csB.x + fx * snB.x) + q4.y * (kB.y * csB.y + fy * snB.y)
               + q4.z * (kB.z * csB.z + fz * snB.z) + q4.w * (kB.w * csB.w + fw * snB.w);
        }
#pragma unroll
        for (int o = 16; o; o >>= 1) {
            dA += __shfl_xor_sync(0xffffffffu, dA, o);
            dB += __shfl_xor_sync(0xffffffffu, dB, o);
        }
        if (lane == 0) { s_sc[cA] = dA; s_sc[cB] = dB; }
    }
    for (; c0 < L; c0 += 8) {
        const float* krow = (c0 == ii) ? knew : (kbp + (size_t)c0 * DK);
        float4 kv = ((const float4*)krow)[lane];
        int pos;
        if (seq < MAXC) pos = c0;
        else pos = (c0 < SINK) ? c0
                 : (c0 > ii)   ? (SINK + c0 - ii - 1)
                               : (c0 + (MAXC - 1 - ii));
        float4 cs = ((const float4*)(g_cos + pos * 64))[j16];
        float4 sn = ((const float4*)(g_sin + pos * 64))[j16];
        float fx = sgn * __shfl_xor_sync(0xffffffffu, kv.x, 16);
        float fy = sgn * __shfl_xor_sync(0xffffffffu, kv.y, 16);
        float fz = sgn * __shfl_xor_sync(0xffffffffu, kv.z, 16);
        float fw = sgn * __shfl_xor_sync(0xffffffffu, kv.w, 16);
        float d = q4.x * (kv.x * cs.x + fx * sn.x) + q4.y * (kv.y * cs.y + fy * sn.y)
                + q4.z * (kv.z * cs.z + fz * sn.z) + q4.w * (kv.w * cs.w + fw * sn.w);
#pragma unroll
        for (int o = 16; o; o >>= 1) d += __shfl_xor_sync(0xffffffffu, d, o);
        if (lane == 0) s_sc[c0] = d;
    }
    __syncthreads();

    // ---- softmax (max, exp, sum) ----
    float lmax = -1e30f;
    for (int c = tid; c < L; c += 256) lmax = fmaxf(lmax, s_sc[c]);
#pragma unroll
    for (int o = 16; o; o >>= 1) lmax = fmaxf(lmax, __shfl_xor_sync(0xffffffffu, lmax, o));
    if (lane == 0) s_red[warp] = lmax;
    __syncthreads();
    if (warp == 0) {
        float m = (lane < 8) ? s_red[lane] : -1e30f;
#pragma unroll
        for (int o = 4; o; o >>= 1) m = fmaxf(m, __shfl_xor_sync(0xffffffffu, m, o));
        if (lane == 0) s_b[0] = m;
    }
    __syncthreads();
    const float gmax = s_b[0];

    float lsum = 0.0f;
    for (int c = tid; c < L; c += 256) {
        float e = __expf(s_sc[c] - gmax);
        s_sc[c] = e;
        lsum += e;
    }
#pragma unroll
    for (int o = 16; o; o >>= 1) lsum += __shfl_xor_sync(0xffffffffu, lsum, o);
    if (lane == 0) s_red[warp] = lsum;
    __syncthreads();
    if (warp == 0) {
        float m = (lane < 8) ? s_red[lane] : 0.0f;
#pragma unroll
        for (int o = 4; o; o >>= 1) m += __shfl_xor_sync(0xffffffffu, m, o);
        if (lane == 0) s_b[1] = m;
    }
    __syncthreads();
    const float inv = 1.0f / s_b[1];

    // ---- AV: 128 dims x 2 c-parity groups, 8 rows in flight per thread ----
    const int d    = tid & 127;
    const int half = tid >> 7;
    const float* vbp  = vcache + (size_t)bh * MAXC * DK;
    const float* vnew = g_Vn + b * DM + h * DK;
    float a0 = 0.0f, a1 = 0.0f, a2 = 0.0f, a3 = 0.0f;
    int c = half;
    for (; c + 14 < L; c += 16) {
        const float* r0 = (c      == ii) ? vnew : vbp + (size_t)(c     ) * DK;
        const float* r1 = (c + 2  == ii) ? vnew : vbp + (size_t)(c + 2 ) * DK;
        const float* r2 = (c + 4  == ii) ? vnew : vbp + (size_t)(c + 4 ) * DK;
        const float* r3 = (c + 6  == ii) ? vnew : vbp + (size_t)(c + 6 ) * DK;
        const float* r4 = (c + 8  == ii) ? vnew : vbp + (size_t)(c + 8 ) * DK;
        const float* r5 = (c + 10 == ii) ? vnew : vbp + (size_t)(c + 10) * DK;
        const float* r6 = (c + 12 == ii) ? vnew : vbp + (size_t)(c + 12) * DK;
        const float* r7 = (c + 14 == ii) ? vnew : vbp + (size_t)(c + 14) * DK;
        float v0 = r0[d], v1 = r1[d], v2 = r2[d], v3 = r3[d];
        float v4 = r4[d], v5 = r5[d], v6 = r6[d], v7 = r7[d];
        a0 += s_sc[c     ] * v0;
        a1 += s_sc[c + 2 ] * v1;
        a2 += s_sc[c + 4 ] * v2;
        a3 += s_sc[c + 6 ] * v3;
        a0 += s_sc[c + 8 ] * v4;
        a1 += s_sc[c + 10] * v5;
        a2 += s_sc[c + 12] * v6;
        a3 += s_sc[c + 14] * v7;
    }
    for (; c < L; c += 2) {
        const float* vr = (c == ii) ? vnew : vbp + (size_t)c * DK;
        a0 += s_sc[c] * vr[d];
    }
    s_acc[half][d] = (a0 + a1) + (a2 + a3);
    __syncthreads();
    if (tid < DK)
        g_ctx[b * DM + h * DK + tid] = (s_acc[0][tid] + s_acc[1][tid]) * inv;
}

// ---------------- launch ----------------
extern "C" void kernel_launch(void* const* d_in, const int* in_sizes, int n_in,
                              void* d_out, int out_size)
{
    const float* x_new   = (const float*)d_in[0];
    const float* k_cache = (const float*)d_in[1];
    const float* v_cache = (const float*)d_in[2];
    const float* W_Q     = (const float*)d_in[3];
    const float* W_K     = (const float*)d_in[4];
    const float* W_V     = (const float*)d_in[5];
    const float* W_O     = (const float*)d_in[6];
    const int*   seq_len = (const int*)  d_in[7];
    float* out = (float*)d_out;

    // 1. RoPE cos/sin table (1024 x 64)
    rope_table_kernel<<<256, 256>>>();

    // 2. QKV projections: 3 weights x 8 k-splits of 512
    skinny_gemm_kernel<<<dim3(DM / 128, 3, 8), 128>>>(x_new, W_Q, W_K, W_V, 512);
    qkv_reduce_kernel<<<(3 * BB * DM) / 256, 256>>>();

    // 3. attention over the streaming window (no physical reorder needed)
    attn_kernel<<<dim3(HH, BB), 256>>>(k_cache, v_cache, seq_len);

    // 4. output projection: 1 weight x 8 k-splits of 512, then reduce into d_out
    skinny_gemm_kernel<<<dim3(DM / 128, 1, 8), 128>>>(nullptr, W_O, W_O, W_O, 512);
    o_reduce_kernel<<<(BB * DM) / 256, 256>>>(out);
}

// round 3
// speedup vs baseline: 2.0594x; 1.4712x over previous
#include <cuda_runtime.h>
#include <math.h>

#define BB 32
#define HH 32
#define DM 4096
#define DK 128
#define SINK 4
#define WINDOW 1020
#define MAXC (SINK + WINDOW)   // 1024

// ---------------- device scratch (no allocs allowed) ----------------
__device__ float g_Q  [BB * DM];
__device__ float g_Kn [BB * DM];
__device__ float g_Vn [BB * DM];
__device__ float g_ctx[BB * DM];
__device__ float g_part[48 * BB * DM];    // 3 weights * 16 ksplit slabs
__device__ float g_cos[MAXC * 64];
__device__ float g_sin[MAXC * 64];

// ---------------- helpers: packed f32x2 FMA ----------------
__device__ __forceinline__ unsigned long long pk2(float a, float b) {
    unsigned long long r;
    asm("mov.b64 %0, {%1, %2};" : "=l"(r) : "f"(a), "f"(b));
    return r;
}
__device__ __forceinline__ void fma2(unsigned long long &acc, unsigned long long x, unsigned long long w) {
    asm("fma.rn.f32x2 %0, %1, %2, %0;" : "+l"(acc) : "l"(x), "l"(w));
}
__device__ __forceinline__ float2 upk2(unsigned long long v) {
    float2 r;
    asm("mov.b64 {%0, %1}, %2;" : "=f"(r.x), "=f"(r.y) : "l"(v));
    return r;
}

// ---------------- RoPE cos/sin table: pos in [0,1024), j in [0,64) ----------------
__global__ void rope_table_kernel() {
    int idx = blockIdx.x * 256 + threadIdx.x;   // 65536 entries
    int pos = idx >> 6;
    int j   = idx & 63;
    float theta = powf(10000.0f, -(float)j / 64.0f);
    float m = (float)pos * theta;
    float s, c;
    sincosf(m, &s, &c);
    g_cos[idx] = c;
    g_sin[idx] = s;
}

// ---------------- skinny GEMM: out[b][n] = sum_k X[b][k] * W[n][k] ----------------
// block: 128 threads, covers 256 n (2 per thread), all 32 b, klen k.
// Weight tile staged in smem with coalesced LDG (critical: direct per-thread row
// streaming costs 32 L1tex wavefronts per warp load).
#define GCK 32
#define XPITCH 34
#define WPITCH 36
#define NPB 256
#define KS 16

__global__ void __launch_bounds__(128) skinny_gemm_kernel(
                                   const float* __restrict__ X,
                                   const float* __restrict__ W0,
                                   const float* __restrict__ W1,
                                   const float* __restrict__ W2,
                                   int klen)
{
    __shared__ float xs[GCK * XPITCH];   // x tile  [k][b]
    __shared__ float ws[NPB * WPITCH];   // w tile  [n][k]
    const float* Xp = X ? X : g_ctx;
    const float* W  = (blockIdx.y == 0) ? W0 : (blockIdx.y == 1) ? W1 : W2;
    const int tid   = threadIdx.x;
    const int nbase = blockIdx.x * NPB;
    const int kbase = blockIdx.z * klen;

    unsigned long long acc0[16], acc1[16];
#pragma unroll
    for (int p = 0; p < 16; p++) { acc0[p] = 0ull; acc1[p] = 0ull; }

    for (int kc = 0; kc < klen; kc += GCK) {
        // stage x tile: 32k x 32b, coalesced over k
#pragma unroll
        for (int i = 0; i < 8; i++) {
            int idx = tid + i * 128;
            int k = idx & 31, b = idx >> 5;
            xs[k * XPITCH + b] = Xp[b * DM + kbase + kc + k];
        }
        // stage w tile: 256 rows x 8 float4, coalesced 128B per row
#pragma unroll
        for (int i = 0; i < 16; i++) {
            int idx = tid + i * 128;
            int r = idx >> 3, s = idx & 7;
            *(float4*)&ws[r * WPITCH + 4 * s] =
                *(const float4*)&W[(size_t)(nbase + r) * DM + kbase + kc + 4 * s];
        }
        __syncthreads();

#pragma unroll
        for (int k4 = 0; k4 < GCK / 4; k4++) {
            float4 w0 = *(float4*)&ws[tid * WPITCH + 4 * k4];
            float4 w1 = *(float4*)&ws[(tid + 128) * WPITCH + 4 * k4];
            float w0a[4] = {w0.x, w0.y, w0.z, w0.w};
            float w1a[4] = {w1.x, w1.y, w1.z, w1.w};
#pragma unroll
            for (int j = 0; j < 4; j++) {
                const unsigned long long* x =
                    (const unsigned long long*)(xs + (4 * k4 + j) * XPITCH);
                unsigned long long p0 = pk2(w0a[j], w0a[j]);
                unsigned long long p1 = pk2(w1a[j], w1a[j]);
#pragma unroll
                for (int p = 0; p < 16; p++) {
                    unsigned long long xv = x[p];
                    fma2(acc0[p], xv, p0);
                    fma2(acc1[p], xv, p1);
                }
            }
        }
        __syncthreads();
    }

    const int slab = (blockIdx.y * gridDim.z + blockIdx.z) * (BB * DM);
#pragma unroll
    for (int p = 0; p < 16; p++) {
        float2 v0 = upk2(acc0[p]);
        float2 v1 = upk2(acc1[p]);
        g_part[slab + (2 * p)     * DM + nbase + tid]       = v0.x;
        g_part[slab + (2 * p + 1) * DM + nbase + tid]       = v0.y;
        g_part[slab + (2 * p)     * DM + nbase + 128 + tid] = v1.x;
        g_part[slab + (2 * p + 1) * DM + nbase + 128 + tid] = v1.y;
    }
}

// reduce 16 k-split partials for the 3 QKV projections into g_Q / g_Kn / g_Vn
__global__ void qkv_reduce_kernel() {
    int i = blockIdx.x * 256 + threadIdx.x;   // 3 * 32 * 4096 = 393216
    int y = i / (BB * DM);
    int r = i - y * (BB * DM);
    float v = 0.0f;
#pragma unroll
    for (int z = 0; z < KS; z++) v += g_part[(y * KS + z) * (BB * DM) + r];
    float* dst = (y == 0) ? g_Q : (y == 1) ? g_Kn : g_Vn;
    dst[r] = v;
}

// reduce 16 k-split partials for the output projection straight into d_out
__global__ void o_reduce_kernel(float* __restrict__ out) {
    int i = blockIdx.x * 256 + threadIdx.x;   // 131072
    float v = 0.0f;
#pragma unroll
    for (int z = 0; z < KS; z++) v += g_part[z * (BB * DM) + i];
    out[i] = v;
}

// ---------------- attention: one block per (b, h), single-pass online softmax ----------------
__global__ void __launch_bounds__(256) attn_kernel(
                            const float* __restrict__ kcache,
                            const float* __restrict__ vcache,
                            const int* __restrict__ seqp)
{
    __shared__ float s_q[DK];
    __shared__ float s_qr[DK];
    __shared__ float s_m[8];
    __shared__ float s_l[8];
    __shared__ float s_acc[8][DK + 4];

    const int h = blockIdx.x, b = blockIdx.y;
    const int tid  = threadIdx.x;
    const int lane = tid & 31;
    const int warp = tid >> 5;

    const int seq = *seqp;
    int L, ii;
    if (seq < MAXC) { L = seq + 1; ii = seq; }
    else            { L = MAXC;    ii = SINK + (seq - SINK) % WINDOW; }
    const int qpos = L - 1;
    const int bh = b * HH + h;

    // ---- load + RoPE Q (position qpos), fold in 1/sqrt(DK) ----
    if (tid < DK) s_q[tid] = g_Q[b * DM + h * DK + tid];
    __syncthreads();
    if (tid < DK) {
        int j = tid & 63;
        float flip = (tid < 64) ? -s_q[tid + 64] : s_q[tid - 64];
        float c = g_cos[qpos * 64 + j];
        float s = g_sin[qpos * 64 + j];
        s_qr[tid] = (s_q[tid] * c + flip * s) * 0.08838834764831843f;  // 1/sqrt(128)
    }
    __syncthreads();

    const float4 q4 = ((const float4*)s_qr)[lane];
    const float  sgn = (lane < 16) ? -1.0f : 1.0f;
    const int    j16 = lane & 15;
    const float* kbp  = kcache + (size_t)bh * MAXC * DK;
    const float* vbp  = vcache + (size_t)bh * MAXC * DK;
    const float* knew = g_Kn + b * DM + h * DK;
    const float* vnew = g_Vn + b * DM + h * DK;

    float m = -1e30f, l = 0.0f;
    float4 a = make_float4(0.f, 0.f, 0.f, 0.f);

    int c = warp;
    for (; c + 8 < L; c += 16) {
        const int cA = c, cB = c + 8;
        const float4* krA = (const float4*)((cA == ii) ? knew : kbp + (size_t)cA * DK);
        const float4* krB = (const float4*)((cB == ii) ? knew : kbp + (size_t)cB * DK);
        const float4* vrA = (const float4*)((cA == ii) ? vnew : vbp + (size_t)cA * DK);
        const float4* vrB = (const float4*)((cB == ii) ? vnew : vbp + (size_t)cB * DK);
        float4 kA = __ldcs(krA + lane);
        float4 kB = __ldcs(krB + lane);
        float4 vA = __ldcs(vrA + lane);
        float4 vB = __ldcs(vrB + lane);
        int pA, pB;
        if (seq < MAXC) { pA = cA; pB = cB; }
        else {
            pA = (cA < SINK) ? cA : (cA > ii) ? (SINK + cA - ii - 1) : (cA + (MAXC - 1 - ii));
            pB = (cB < SINK) ? cB : (cB > ii) ? (SINK + cB - ii - 1) : (cB + (MAXC - 1 - ii));
        }
        float4 csA = ((const float4*)(g_cos + pA * 64))[j16];
        float4 snA = ((const float4*)(g_sin + pA * 64))[j16];
        float4 csB = ((const float4*)(g_cos + pB * 64))[j16];
        float4 snB = ((const float4*)(g_sin + pB * 64))[j16];
        float dA, dB;
        {
            float fx = sgn * __shfl_xor_sync(0xffffffffu, kA.x, 16);
            float fy = sgn * __shfl_xor_sync(0xffffffffu, kA.y, 16);
            float fz = sgn * __shfl_xor_sync(0xffffffffu, kA.z, 16);
            float fw = sgn * __shfl_xor_sync(0xffffffffu, kA.w, 16);
            dA = q4.x * (kA.x * csA.x + fx * snA.x) + q4.y * (kA.y * csA.y + fy * snA.y)
               + q4.z * (kA.z * csA.z + fz * snA.z) + q4.w * (kA.w * csA.w + fw * snA.w);
        }
        {
            float fx = sgn * __shfl_xor_sync(0xffffffffu, kB.x, 16);
            float fy = sgn * __shfl_xor_sync(0xffffffffu, kB.y, 16);
            float fz = sgn * __shfl_xor_sync(0xffffffffu, kB.z, 16);
            float fw = sgn * __shfl_xor_sync(0xffffffffu, kB.w, 16);
            dB = q4.x * (kB.x * csB.x + fx * snB.x) + q4.y * (kB.y * csB.y + fy * snB.y)
               + q4.z * (kB.z * csB.z + fz * snB.z) + q4.w * (kB.w * csB.w + fw * snB.w);
        }
#pragma unroll
        for (int o = 16; o; o >>= 1) {
            dA += __shfl_xor_sync(0xffffffffu, dA, o);
            dB += __shfl_xor_sync(0xffffffffu, dB, o);
        }
        float mn = fmaxf(m, fmaxf(dA, dB));
        float sc = __expf(m - mn);
        float eA = __expf(dA - mn);
        float eB = __expf(dB - mn);
        l = l * sc + eA + eB;
        a.x = a.x * sc + eA * vA.x + eB * vB.x;
        a.y = a.y * sc + eA * vA.y + eB * vB.y;
        a.z = a.z * sc + eA * vA.z + eB * vB.z;
        a.w = a.w * sc + eA * vA.w + eB * vB.w;
        m = mn;
    }
    for (; c < L; c += 8) {
        const float4* kr = (const float4*)((c == ii) ? knew : kbp + (size_t)c * DK);
        const float4* vr = (const float4*)((c == ii) ? vnew : vbp + (size_t)c * DK);
        float4 kv = __ldcs(kr + lane);
        float4 vv = __ldcs(vr + lane);
        int pos;
        if (seq < MAXC) pos = c;
        else pos = (c < SINK) ? c
                 : (c > ii)   ? (SINK + c - ii - 1)
                              : (c + (MAXC - 1 - ii));
        float4 cs = ((const float4*)(g_cos + pos * 64))[j16];
        float4 sn = ((const float4*)(g_sin + pos * 64))[j16];
        float fx = sgn * __shfl_xor_sync(0xffffffffu, kv.x, 16);
        float fy = sgn * __shfl_xor_sync(0xffffffffu, kv.y, 16);
        float fz = sgn * __shfl_xor_sync(0xffffffffu, kv.z, 16);
        float fw = sgn * __shfl_xor_sync(0xffffffffu, kv.w, 16);
        float d = q4.x * (kv.x * cs.x + fx * sn.x) + q4.y * (kv.y * cs.y + fy * sn.y)
                + q4.z * (kv.z * cs.z + fz * sn.z) + q4.w * (kv.w * cs.w + fw * sn.w);
#pragma unroll
        for (int o = 16; o; o >>= 1) d += __shfl_xor_sync(0xffffffffu, d, o);
        float mn = fmaxf(m, d);
        float sc = __expf(m - mn);
        float e  = __expf(d - mn);
        l = l * sc + e;
        a.x = a.x * sc + e * vv.x;
        a.y = a.y * sc + e * vv.y;
        a.z = a.z * sc + e * vv.z;
        a.w = a.w * sc + e * vv.w;
        m = mn;
    }

    // ---- combine 8 warps ----
    if (lane == 0) { s_m[warp] = m; s_l[warp] = l; }
    *(float4*)&s_acc[warp][4 * lane] = a;
    __syncthreads();
    if (tid < DK) {
        float M = s_m[0];
#pragma unroll
        for (int w = 1; w < 8; w++) M = fmaxf(M, s_m[w]);
        float den = 0.0f, val = 0.0f;
#pragma unroll
        for (int w = 0; w < 8; w++) {
            float e = __expf(s_m[w] - M);
            den += e * s_l[w];
            val += e * s_acc[w][tid];
        }
        g_ctx[b * DM + h * DK + tid] = val / den;
    }
}

// ---------------- launch ----------------
extern "C" void kernel_launch(void* const* d_in, const int* in_sizes, int n_in,
                              void* d_out, int out_size)
{
    const float* x_new   = (const float*)d_in[0];
    const float* k_cache = (const float*)d_in[1];
    const float* v_cache = (const float*)d_in[2];
    const float* W_Q     = (const float*)d_in[3];
    const float* W_K     = (const float*)d_in[4];
    const float* W_V     = (const float*)d_in[5];
    const float* W_O     = (const float*)d_in[6];
    const int*   seq_len = (const int*)  d_in[7];
    float* out = (float*)d_out;

    // 1. RoPE cos/sin table (1024 x 64)
    rope_table_kernel<<<256, 256>>>();

    // 2. QKV projections: 3 weights x 16 k-splits of 256
    skinny_gemm_kernel<<<dim3(DM / NPB, 3, KS), 128>>>(x_new, W_Q, W_K, W_V, DM / KS);
    qkv_reduce_kernel<<<(3 * BB * DM) / 256, 256>>>();

    // 3. attention over the streaming window (single-pass online softmax)
    attn_kernel<<<dim3(HH, BB), 256>>>(k_cache, v_cache, seq_len);

    // 4. output projection: 1 weight x 16 k-splits of 256, then reduce into d_out
    skinny_gemm_kernel<<<dim3(DM / NPB, 1, KS), 128>>>(nullptr, W_O, W_O, W_O, DM / KS);
    o_reduce_kernel<<<(BB * DM) / 256, 256>>>(out);
}